// round 1
// baseline (speedup 1.0000x reference)
#include <cuda_runtime.h>
#include <cstdint>

// ---------------------------------------------------------------------------
// HSLSTMRegressor: 2-layer LSTM (B=256, T=512, I=64, H=512) + linear head + MSE
// Persistent single-kernel design:
//   - 128 CTAs x 256 threads, all co-resident; software grid barrier
//   - tf32 mma.sync m16n8k8, gate-fused tiles (each CTA: 128 rows x 8 units x 4 gates)
//   - weights repacked once per launch into mma-fragment layout (coalesced LDG.128)
//   - h state double-buffered, read via .cg (L2-coherent) loads
// ---------------------------------------------------------------------------

#define BATCH 256
#define TT    512
#define II    64
#define HH    512
#define G4    2048
#define NCTA  128
#define NTHREADS 256
#define NK16_0 36   // (64 + 512) / 16
#define NK16_1 64   // (512 + 512) / 16

// Static device scratch (allocation-free rule): ~16 MB total
__device__ uint4 g_Wp0[64 * 4 * NK16_0 * 32];   // 4.5 MB packed layer0 weights (tf32 bits)
__device__ uint4 g_Wp1[64 * 4 * NK16_1 * 32];   // 8.0 MB packed layer1 weights
__device__ float g_bias0[G4];
__device__ float g_bias1[G4];
__device__ float g_h0[2][BATCH * HH];
__device__ float g_c0[BATCH * HH];
__device__ float g_h1[2][BATCH * HH];
__device__ float g_c1[BATCH * HH];
__device__ unsigned g_bar = 0;                  // grid barrier counter (reset at kernel end)

__device__ __forceinline__ unsigned f2tf(float f) {
    unsigned u;
    asm("cvt.rna.tf32.f32 %0, %1;" : "=r"(u) : "f"(f));
    return u;
}

__device__ __forceinline__ void mma_tf32(float* c,
                                         unsigned a0, unsigned a1, unsigned a2, unsigned a3,
                                         unsigned b0, unsigned b1) {
    asm volatile(
        "mma.sync.aligned.m16n8k8.row.col.f32.tf32.tf32.f32 "
        "{%0,%1,%2,%3},{%4,%5,%6,%7},{%8,%9},{%0,%1,%2,%3};"
        : "+f"(c[0]), "+f"(c[1]), "+f"(c[2]), "+f"(c[3])
        : "r"(a0), "r"(a1), "r"(a2), "r"(a3), "r"(b0), "r"(b1));
}

template <bool CG>
__device__ __forceinline__ float4 ld4(const float* p) {
    if (CG) return __ldcg((const float4*)p);
    return __ldg((const float4*)p);
}

__device__ __forceinline__ float sigf(float x) {
    return __fdividef(1.0f, 1.0f + __expf(-x));
}
__device__ __forceinline__ float tanh_(float x) {
    float e = __expf(-2.0f * fabsf(x));
    float r = __fdividef(1.0f - e, 1.0f + e);
    return copysignf(r, x);
}

__device__ __forceinline__ void gsync(unsigned& barn) {
    __threadfence();
    __syncthreads();
    if (threadIdx.x == 0) {
        atomicAdd(&g_bar, 1u);
        unsigned tgt = barn + (unsigned)gridDim.x;
        while (*(volatile unsigned*)&g_bar < tgt) {}
        __threadfence();
    }
    barn += (unsigned)gridDim.x;
    __syncthreads();
}

// GEMM over k16 blocks [kk0, kk1). A is the activation matrix (row-major,
// strideA floats per row); logical A column for block kk is (kk-kk0)*16 + perm.
// wp points at this CTA's packed weight base + lane. Both A and B fragments use
// the same k-permutation within each k16 block, so dot products are exact.
template <bool CG, int NK16>
__device__ __forceinline__ void gemm_span(float acc[4][4],
                                          const uint4* __restrict__ wp,
                                          int kk0, int kk1,
                                          const float* __restrict__ A, int strideA,
                                          int rA, int rB, int tig) {
#pragma unroll 2
    for (int kk = kk0; kk < kk1; ++kk) {
        const int colb = (kk - kk0) * 16 + tig * 4;
        float4 va = ld4<CG>(A + rA * strideA + colb);
        float4 vb = ld4<CG>(A + rB * strideA + colb);
        uint4 q0 = __ldg(&wp[(0 * NK16 + kk) * 32]);
        uint4 q1 = __ldg(&wp[(1 * NK16 + kk) * 32]);
        uint4 q2 = __ldg(&wp[(2 * NK16 + kk) * 32]);
        uint4 q3 = __ldg(&wp[(3 * NK16 + kk) * 32]);
        unsigned ax0 = f2tf(va.x), ax1 = f2tf(va.y), ax2 = f2tf(va.z), ax3 = f2tf(va.w);
        unsigned bx0 = f2tf(vb.x), bx1 = f2tf(vb.y), bx2 = f2tf(vb.z), bx3 = f2tf(vb.w);
        mma_tf32(acc[0], ax0, bx0, ax1, bx1, q0.x, q0.y);
        mma_tf32(acc[0], ax2, bx2, ax3, bx3, q0.z, q0.w);
        mma_tf32(acc[1], ax0, bx0, ax1, bx1, q1.x, q1.y);
        mma_tf32(acc[1], ax2, bx2, ax3, bx3, q1.z, q1.w);
        mma_tf32(acc[2], ax0, bx0, ax1, bx1, q2.x, q2.y);
        mma_tf32(acc[2], ax2, bx2, ax3, bx3, q2.z, q2.w);
        mma_tf32(acc[3], ax0, bx0, ax1, bx1, q3.x, q3.y);
        mma_tf32(acc[3], ax2, bx2, ax3, bx3, q3.z, q3.w);
    }
}

__device__ __forceinline__ void cell_update(float acc[4][4],
                                            const float* __restrict__ bias,
                                            float* __restrict__ cbuf,
                                            float* __restrict__ hout,
                                            int rA, int rB, int cA) {
#pragma unroll
    for (int p = 0; p < 4; ++p) {
        int r = (p < 2) ? rA : rB;
        int c = cA + (p & 1);
        float gi = acc[0][p] + __ldg(&bias[c]);
        float gf = acc[1][p] + __ldg(&bias[HH + c]);
        float gg = acc[2][p] + __ldg(&bias[2 * HH + c]);
        float go = acc[3][p] + __ldg(&bias[3 * HH + c]);
        float cold = cbuf[r * HH + c];
        float cn = sigf(gf) * cold + sigf(gi) * tanh_(gg);
        cbuf[r * HH + c] = cn;
        __stcg(&hout[r * HH + c], sigf(go) * tanh_(cn));
    }
}

__global__ void __launch_bounds__(NTHREADS, 1)
lstm_kernel(const float* __restrict__ x, const float* __restrict__ y,
            const float* __restrict__ Wih0, const float* __restrict__ Whh0,
            const float* __restrict__ bih0, const float* __restrict__ bhh0,
            const float* __restrict__ Wih1, const float* __restrict__ Whh1,
            const float* __restrict__ bih1, const float* __restrict__ bhh1,
            const float* __restrict__ Wlin, const float* __restrict__ blin,
            float* __restrict__ dout, int out_size) {
    const int tid = threadIdx.x;
    const int gtid = blockIdx.x * NTHREADS + tid;
    const int GSTRIDE = NCTA * NTHREADS;

    // ---------------- prologue: pack weights, combine biases, zero state -----
    // Packed element for (ub,g,kk,lane): W[n][k16+4*tig .. +3], n = g*512+ub*8+grp.
    for (int idx = gtid; idx < 64 * 4 * NK16_0 * 32; idx += GSTRIDE) {
        int lane = idx & 31;
        int kk = (idx >> 5) % NK16_0;
        int gu = idx / (32 * NK16_0);
        int g = gu & 3;
        int ub2 = gu >> 2;
        int n = g * HH + ub2 * 8 + (lane >> 2);
        int k = kk * 16 + (lane & 3) * 4;
        float v[4];
#pragma unroll
        for (int j = 0; j < 4; ++j) {
            int kj = k + j;
            v[j] = (kj < II) ? __ldg(&Wih0[n * II + kj]) : __ldg(&Whh0[n * HH + (kj - II)]);
        }
        g_Wp0[idx] = make_uint4(f2tf(v[0]), f2tf(v[1]), f2tf(v[2]), f2tf(v[3]));
    }
    for (int idx = gtid; idx < 64 * 4 * NK16_1 * 32; idx += GSTRIDE) {
        int lane = idx & 31;
        int kk = (idx >> 5) % NK16_1;
        int gu = idx / (32 * NK16_1);
        int g = gu & 3;
        int ub2 = gu >> 2;
        int n = g * HH + ub2 * 8 + (lane >> 2);
        int k = kk * 16 + (lane & 3) * 4;
        float v[4];
#pragma unroll
        for (int j = 0; j < 4; ++j) {
            int kj = k + j;
            v[j] = (kj < HH) ? __ldg(&Wih1[n * HH + kj]) : __ldg(&Whh1[n * HH + (kj - HH)]);
        }
        g_Wp1[idx] = make_uint4(f2tf(v[0]), f2tf(v[1]), f2tf(v[2]), f2tf(v[3]));
    }
    for (int i = gtid; i < G4; i += GSTRIDE) {
        g_bias0[i] = bih0[i] + bhh0[i];
        g_bias1[i] = bih1[i] + bhh1[i];
    }
    for (int i = gtid; i < BATCH * HH; i += GSTRIDE) {
        g_h0[0][i] = 0.0f;
        g_h1[0][i] = 0.0f;
        g_c0[i] = 0.0f;
        g_c1[i] = 0.0f;
    }

    unsigned barn = 0;
    gsync(barn);

    // ---------------- recurrence ---------------------------------------------
    const int lane = tid & 31;
    const int w = tid >> 5;
    const int grp = lane >> 2;
    const int tig = lane & 3;
    const int mtile = blockIdx.x >> 6;   // 0..1
    const int ub = blockIdx.x & 63;      // 0..63
    const int m0 = mtile * 128;
    const int u0 = ub * 8;
    const int rA = m0 + w * 16 + grp;
    const int rB = rA + 8;
    const int cA = u0 + 2 * tig;
    const uint4* wp0 = g_Wp0 + (size_t)(ub * 4 * NK16_0) * 32 + lane;
    const uint4* wp1 = g_Wp1 + (size_t)(ub * 4 * NK16_1) * 32 + lane;

    const float* h0r = g_h0[0];
    float* h0w = g_h0[1];
    const float* h1r = g_h1[0];
    float* h1w = g_h1[1];

    for (int t = 0; t < TT; ++t) {
        // ---- layer 0: gates = [x_t | h0] @ W0^T ----
        float acc[4][4];
#pragma unroll
        for (int a = 0; a < 4; ++a)
#pragma unroll
            for (int b = 0; b < 4; ++b) acc[a][b] = 0.0f;
        gemm_span<false, NK16_0>(acc, wp0, 0, 4, x + t * II, TT * II, rA, rB, tig);
        gemm_span<true, NK16_0>(acc, wp0, 4, NK16_0, h0r, HH, rA, rB, tig);
        cell_update(acc, g_bias0, g_c0, h0w, rA, rB, cA);
        gsync(barn);

        // ---- layer 1: gates = [h0_new | h1] @ W1^T ----
#pragma unroll
        for (int a = 0; a < 4; ++a)
#pragma unroll
            for (int b = 0; b < 4; ++b) acc[a][b] = 0.0f;
        gemm_span<true, NK16_1>(acc, wp1, 0, 32, h0w, HH, rA, rB, tig);
        gemm_span<true, NK16_1>(acc, wp1, 32, NK16_1, h1r, HH, rA, rB, tig);
        cell_update(acc, g_bias1, g_c1, h1w, rA, rB, cA);

        // swap double buffers
        {
            const float* tmp = h0r; h0r = h0w; h0w = (float*)tmp;
            tmp = h1r; h1r = h1w; h1w = (float*)tmp;
        }

        if (t < TT - 1) gsync(barn);
    }

    // ---------------- final barrier: non-zero CTAs arrive and exit ----------
    __threadfence();
    __syncthreads();
    if (tid == 0) atomicAdd(&g_bar, 1u);
    barn += NCTA;
    if (blockIdx.x != 0) return;

    if (tid == 0) {
        while (*(volatile unsigned*)&g_bar < barn) {}
        __threadfence();
        *(volatile unsigned*)&g_bar = 0u;  // reset for next graph replay
    }
    __syncthreads();

    // ---------------- epilogue on CTA 0: linear head + MSE loss --------------
    int b = tid;  // 0..255 = batch row
    const float* hrow = h1r + b * HH;
    float s = __ldg(&blin[0]);
#pragma unroll 8
    for (int c2 = 0; c2 < HH; c2 += 4) {
        float4 h4 = __ldcg((const float4*)(hrow + c2));
        s += h4.x * __ldg(&Wlin[c2]) + h4.y * __ldg(&Wlin[c2 + 1]) +
             h4.z * __ldg(&Wlin[c2 + 2]) + h4.w * __ldg(&Wlin[c2 + 3]);
    }

    __shared__ float red[NTHREADS];
    float d = s - __ldg(&y[b]);
    red[b] = d * d;
    __syncthreads();
#pragma unroll
    for (int off = 128; off > 0; off >>= 1) {
        if (b < off) red[b] += red[b + off];
        __syncthreads();
    }
    float loss = red[0] * (1.0f / BATCH);

    if (out_size >= BATCH + 1) {
        dout[b] = s;
        if (b == 0) dout[BATCH] = loss;
        for (int i2 = BATCH + 1 + b; i2 < out_size; i2 += NTHREADS) dout[i2] = 0.0f;
    } else if (out_size == BATCH) {
        dout[b] = s;
    } else if (out_size == 1) {
        if (b == 0) dout[0] = loss;
    } else {
        if (b < out_size) dout[b] = (b < BATCH) ? s : loss;
    }
}

extern "C" void kernel_launch(void* const* d_in, const int* in_sizes, int n_in,
                              void* d_out, int out_size) {
    const float* x    = (const float*)d_in[0];
    const float* y    = (const float*)d_in[1];
    const float* Wih0 = (const float*)d_in[2];
    const float* Whh0 = (const float*)d_in[3];
    const float* bih0 = (const float*)d_in[4];
    const float* bhh0 = (const float*)d_in[5];
    const float* Wih1 = (const float*)d_in[6];
    const float* Whh1 = (const float*)d_in[7];
    const float* bih1 = (const float*)d_in[8];
    const float* bhh1 = (const float*)d_in[9];
    const float* Wlin = (const float*)d_in[10];
    const float* blin = (const float*)d_in[11];

    lstm_kernel<<<NCTA, NTHREADS>>>(x, y, Wih0, Whh0, bih0, bhh0,
                                    Wih1, Whh1, bih1, bhh1, Wlin, blin,
                                    (float*)d_out, out_size);
}

// round 2
// speedup vs baseline: 1.7789x; 1.7789x over previous
#include <cuda_runtime.h>
#include <cstdint>

// ---------------------------------------------------------------------------
// HSLSTMRegressor: 2-layer LSTM (B=256, T=512, I=64, H=512) + linear head + MSE
// R2: weights resident in shared memory (packed tf32 fragments, 200KB/CTA),
//     depth-2 prefetch of L2 activation loads, cell state + biases in registers.
//   - 128 CTAs x 256 threads persistent, software grid barrier (2/step)
//   - tf32 mma.sync m16n8k8, gate-fused tiles (CTA: 128 rows x 8 units x 4 gates)
// ---------------------------------------------------------------------------

#define BATCH 256
#define TT    512
#define II    64
#define HH    512
#define NCTA  128
#define NTHREADS 256
#define NK16_0 36   // (64 + 512) / 16
#define NK16_1 64   // (512 + 512) / 16
#define SMEM_W0 (4 * NK16_0 * 32)          // uint4 elements, layer0 slice
#define SMEM_W1 (4 * NK16_1 * 32)          // uint4 elements, layer1 slice
#define SMEM_BYTES ((SMEM_W0 + SMEM_W1) * 16)

__device__ float g_h0[2][BATCH * HH];
__device__ float g_h1[2][BATCH * HH];
__device__ unsigned g_bar = 0;   // grid barrier counter (reset at kernel end)

__device__ __forceinline__ unsigned f2tf(float f) {
    unsigned u;
    asm("cvt.rna.tf32.f32 %0, %1;" : "=r"(u) : "f"(f));
    return u;
}

__device__ __forceinline__ void mma_tf32(float* c,
                                         unsigned a0, unsigned a1, unsigned a2, unsigned a3,
                                         unsigned b0, unsigned b1) {
    asm volatile(
        "mma.sync.aligned.m16n8k8.row.col.f32.tf32.tf32.f32 "
        "{%0,%1,%2,%3},{%4,%5,%6,%7},{%8,%9},{%0,%1,%2,%3};"
        : "+f"(c[0]), "+f"(c[1]), "+f"(c[2]), "+f"(c[3])
        : "r"(a0), "r"(a1), "r"(a2), "r"(a3), "r"(b0), "r"(b1));
}

__device__ __forceinline__ float sigf(float x) {
    return __fdividef(1.0f, 1.0f + __expf(-x));
}
__device__ __forceinline__ float tanh_(float x) {
    float e = __expf(-2.0f * fabsf(x));
    float r = __fdividef(1.0f - e, 1.0f + e);
    return copysignf(r, x);
}

__device__ __forceinline__ void gsync(unsigned& barn) {
    __threadfence();
    __syncthreads();
    if (threadIdx.x == 0) {
        atomicAdd(&g_bar, 1u);
        unsigned tgt = barn + (unsigned)gridDim.x;
        while (*(volatile unsigned*)&g_bar < tgt) {}
        __threadfence();
    }
    barn += (unsigned)gridDim.x;
    __syncthreads();
}

// GEMM over nblk k16 blocks starting at absolute block kk0.
// sW: this CTA's packed weight slice in SMEM, already offset by +lane.
// pA/pB: activation row pointers (already include row base and +tig*4).
// Depth-2 prefetch of the L2 activation float4 stream.
template <int NK16>
__device__ __forceinline__ void gemm_span(float acc[4][4],
                                          const uint4* __restrict__ sW,
                                          int kk0, int nblk,
                                          const float* __restrict__ pA,
                                          const float* __restrict__ pB) {
    float4 a0 = __ldcg((const float4*)pA);
    float4 b0 = __ldcg((const float4*)pB);
    const int j1 = (nblk > 1) ? 1 : 0;
    float4 a1 = __ldcg((const float4*)(pA + j1 * 16));
    float4 b1 = __ldcg((const float4*)(pB + j1 * 16));
#pragma unroll 4
    for (int j = 0; j < nblk; ++j) {
        const int kk = kk0 + j;
        uint4 q0 = sW[(0 * NK16 + kk) * 32];
        uint4 q1 = sW[(1 * NK16 + kk) * 32];
        uint4 q2 = sW[(2 * NK16 + kk) * 32];
        uint4 q3 = sW[(3 * NK16 + kk) * 32];
        const int jn = (j + 2 < nblk) ? (j + 2) : (nblk - 1);
        float4 na = __ldcg((const float4*)(pA + jn * 16));
        float4 nb = __ldcg((const float4*)(pB + jn * 16));
        unsigned ax0 = f2tf(a0.x), ax1 = f2tf(a0.y), ax2 = f2tf(a0.z), ax3 = f2tf(a0.w);
        unsigned bx0 = f2tf(b0.x), bx1 = f2tf(b0.y), bx2 = f2tf(b0.z), bx3 = f2tf(b0.w);
        mma_tf32(acc[0], ax0, bx0, ax1, bx1, q0.x, q0.y);
        mma_tf32(acc[0], ax2, bx2, ax3, bx3, q0.z, q0.w);
        mma_tf32(acc[1], ax0, bx0, ax1, bx1, q1.x, q1.y);
        mma_tf32(acc[1], ax2, bx2, ax3, bx3, q1.z, q1.w);
        mma_tf32(acc[2], ax0, bx0, ax1, bx1, q2.x, q2.y);
        mma_tf32(acc[2], ax2, bx2, ax3, bx3, q2.z, q2.w);
        mma_tf32(acc[3], ax0, bx0, ax1, bx1, q3.x, q3.y);
        mma_tf32(acc[3], ax2, bx2, ax3, bx3, q3.z, q3.w);
        a0 = a1; b0 = b1; a1 = na; b1 = nb;
    }
}

// bias8: per-thread combined biases, layout [gate*2 + (col&1)]
__device__ __forceinline__ void cell_update(float acc[4][4],
                                            const float* __restrict__ bias8,
                                            float* __restrict__ creg,
                                            float* __restrict__ hout,
                                            int rA, int rB, int cA) {
#pragma unroll
    for (int p = 0; p < 4; ++p) {
        int r = (p < 2) ? rA : rB;
        int c = cA + (p & 1);
        float gi = acc[0][p] + bias8[0 + (p & 1)];
        float gf = acc[1][p] + bias8[2 + (p & 1)];
        float gg = acc[2][p] + bias8[4 + (p & 1)];
        float go = acc[3][p] + bias8[6 + (p & 1)];
        float cn = sigf(gf) * creg[p] + sigf(gi) * tanh_(gg);
        creg[p] = cn;
        __stcg(&hout[r * HH + c], sigf(go) * tanh_(cn));
    }
}

__global__ void __launch_bounds__(NTHREADS, 1)
lstm_kernel(const float* __restrict__ x, const float* __restrict__ y,
            const float* __restrict__ Wih0, const float* __restrict__ Whh0,
            const float* __restrict__ bih0, const float* __restrict__ bhh0,
            const float* __restrict__ Wih1, const float* __restrict__ Whh1,
            const float* __restrict__ bih1, const float* __restrict__ bhh1,
            const float* __restrict__ Wlin, const float* __restrict__ blin,
            float* __restrict__ dout, int out_size) {
    extern __shared__ uint4 smw[];
    uint4* sW0base = smw;
    uint4* sW1base = smw + SMEM_W0;

    const int tid = threadIdx.x;
    const int gtid = blockIdx.x * NTHREADS + tid;
    const int GSTRIDE = NCTA * NTHREADS;

    const int lane = tid & 31;
    const int w = tid >> 5;
    const int grp = lane >> 2;
    const int tig = lane & 3;
    const int mtile = blockIdx.x >> 6;   // 0..1
    const int ub = blockIdx.x & 63;      // 0..63
    const int m0 = mtile * 128;
    const int u0 = ub * 8;
    const int rA = m0 + w * 16 + grp;
    const int rB = rA + 8;
    const int cA = u0 + 2 * tig;

    // ------------- prologue: pack this CTA's weight slice into SMEM ---------
    // slot (g, kk, lane) holds W[n][kk*16 + (lane&3)*4 .. +3] as tf32 bits,
    // n = g*512 + u0 + (lane>>2).
    for (int s = tid; s < SMEM_W0; s += NTHREADS) {
        int ln = s & 31;
        int kk = (s >> 5) % NK16_0;
        int g = s / (32 * NK16_0);
        int n = g * HH + u0 + (ln >> 2);
        int k = kk * 16 + (ln & 3) * 4;
        float v[4];
#pragma unroll
        for (int j = 0; j < 4; ++j) {
            int kj = k + j;
            v[j] = (kj < II) ? __ldg(&Wih0[n * II + kj]) : __ldg(&Whh0[n * HH + (kj - II)]);
        }
        sW0base[s] = make_uint4(f2tf(v[0]), f2tf(v[1]), f2tf(v[2]), f2tf(v[3]));
    }
    for (int s = tid; s < SMEM_W1; s += NTHREADS) {
        int ln = s & 31;
        int kk = (s >> 5) % NK16_1;
        int g = s / (32 * NK16_1);
        int n = g * HH + u0 + (ln >> 2);
        int k = kk * 16 + (ln & 3) * 4;
        float v[4];
#pragma unroll
        for (int j = 0; j < 4; ++j) {
            int kj = k + j;
            v[j] = (kj < HH) ? __ldg(&Wih1[n * HH + kj]) : __ldg(&Whh1[n * HH + (kj - HH)]);
        }
        sW1base[s] = make_uint4(f2tf(v[0]), f2tf(v[1]), f2tf(v[2]), f2tf(v[3]));
    }
    // zero initial h state
    for (int i = gtid; i < BATCH * HH; i += GSTRIDE) {
        g_h0[0][i] = 0.0f;
        g_h1[0][i] = 0.0f;
    }

    // per-thread register-resident biases (combined ih+hh)
    float bias8_0[8], bias8_1[8];
#pragma unroll
    for (int g = 0; g < 4; ++g)
#pragma unroll
        for (int q = 0; q < 2; ++q) {
            int n = g * HH + cA + q;
            bias8_0[g * 2 + q] = __ldg(&bih0[n]) + __ldg(&bhh0[n]);
            bias8_1[g * 2 + q] = __ldg(&bih1[n]) + __ldg(&bhh1[n]);
        }

    unsigned barn = 0;
    gsync(barn);   // also covers smem pack visibility within CTA

    const uint4* sW0 = sW0base + lane;
    const uint4* sW1 = sW1base + lane;

    const float* h0r = g_h0[0];
    float* h0w = g_h0[1];
    const float* h1r = g_h1[0];
    float* h1w = g_h1[1];

    float c0reg[4] = {0.f, 0.f, 0.f, 0.f};
    float c1reg[4] = {0.f, 0.f, 0.f, 0.f};

    const float* xA = x + (size_t)rA * (TT * II) + tig * 4;
    const float* xB = x + (size_t)rB * (TT * II) + tig * 4;
    const int oA = rA * HH + tig * 4;
    const int oB = rB * HH + tig * 4;

    for (int t = 0; t < TT; ++t) {
        // ---- layer 0: gates = [x_t | h0] @ W0^T ----
        float acc[4][4];
#pragma unroll
        for (int a = 0; a < 4; ++a)
#pragma unroll
            for (int b = 0; b < 4; ++b) acc[a][b] = 0.0f;
        gemm_span<NK16_0>(acc, sW0, 0, 4, xA + t * II, xB + t * II);
        gemm_span<NK16_0>(acc, sW0, 4, 32, h0r + oA, h0r + oB);
        cell_update(acc, bias8_0, c0reg, h0w, rA, rB, cA);
        gsync(barn);

        // ---- layer 1: gates = [h0_new | h1] @ W1^T ----
#pragma unroll
        for (int a = 0; a < 4; ++a)
#pragma unroll
            for (int b = 0; b < 4; ++b) acc[a][b] = 0.0f;
        gemm_span<NK16_1>(acc, sW1, 0, 32, h0w + oA, h0w + oB);
        gemm_span<NK16_1>(acc, sW1, 32, 32, h1r + oA, h1r + oB);
        cell_update(acc, bias8_1, c1reg, h1w, rA, rB, cA);

        // swap double buffers
        {
            const float* tmp = h0r; h0r = h0w; h0w = (float*)tmp;
            tmp = h1r; h1r = h1w; h1w = (float*)tmp;
        }

        if (t < TT - 1) gsync(barn);
    }

    // ---------------- final barrier: non-zero CTAs arrive and exit ----------
    __threadfence();
    __syncthreads();
    if (tid == 0) atomicAdd(&g_bar, 1u);
    barn += NCTA;
    if (blockIdx.x != 0) return;

    if (tid == 0) {
        while (*(volatile unsigned*)&g_bar < barn) {}
        __threadfence();
        *(volatile unsigned*)&g_bar = 0u;  // reset for next graph replay
    }
    __syncthreads();

    // ---------------- epilogue on CTA 0: linear head + MSE loss --------------
    int b = tid;  // 0..255 = batch row
    const float* hrow = h1r + b * HH;
    float s = __ldg(&blin[0]);
#pragma unroll 8
    for (int c2 = 0; c2 < HH; c2 += 4) {
        float4 h4 = __ldcg((const float4*)(hrow + c2));
        s += h4.x * __ldg(&Wlin[c2]) + h4.y * __ldg(&Wlin[c2 + 1]) +
             h4.z * __ldg(&Wlin[c2 + 2]) + h4.w * __ldg(&Wlin[c2 + 3]);
    }

    __shared__ float red[NTHREADS];
    float d = s - __ldg(&y[b]);
    red[b] = d * d;
    __syncthreads();
#pragma unroll
    for (int off = 128; off > 0; off >>= 1) {
        if (b < off) red[b] += red[b + off];
        __syncthreads();
    }
    float loss = red[0] * (1.0f / BATCH);

    if (out_size >= BATCH + 1) {
        dout[b] = s;
        if (b == 0) dout[BATCH] = loss;
        for (int i2 = BATCH + 1 + b; i2 < out_size; i2 += NTHREADS) dout[i2] = 0.0f;
    } else if (out_size == BATCH) {
        dout[b] = s;
    } else if (out_size == 1) {
        if (b == 0) dout[0] = loss;
    } else {
        if (b < out_size) dout[b] = (b < BATCH) ? s : loss;
    }
}

extern "C" void kernel_launch(void* const* d_in, const int* in_sizes, int n_in,
                              void* d_out, int out_size) {
    const float* x    = (const float*)d_in[0];
    const float* y    = (const float*)d_in[1];
    const float* Wih0 = (const float*)d_in[2];
    const float* Whh0 = (const float*)d_in[3];
    const float* bih0 = (const float*)d_in[4];
    const float* bhh0 = (const float*)d_in[5];
    const float* Wih1 = (const float*)d_in[6];
    const float* Whh1 = (const float*)d_in[7];
    const float* bih1 = (const float*)d_in[8];
    const float* bhh1 = (const float*)d_in[9];
    const float* Wlin = (const float*)d_in[10];
    const float* blin = (const float*)d_in[11];

    cudaFuncSetAttribute(lstm_kernel, cudaFuncAttributeMaxDynamicSharedMemorySize,
                         SMEM_BYTES);
    lstm_kernel<<<NCTA, NTHREADS, SMEM_BYTES>>>(x, y, Wih0, Whh0, bih0, bhh0,
                                                Wih1, Whh1, bih1, bhh1, Wlin, blin,
                                                (float*)d_out, out_size);
}